// round 11
// baseline (speedup 1.0000x reference)
#include <cuda_runtime.h>
#include <cstdint>

// out[b,h,i,j] = mask[b,h,i,j] - |slope[h] * (i - j)|
// B=2, NH=16, L=2048 -> 134,217,728 fp32 = 33,554,432 float4
// slope[h] = 2^(-0.5*(h+1)) for NH=16
//
// FINAL. Pure HBM-streaming kernel: 512 MiB read + 512 MiB write (compulsory
// minimum traffic; bias is register-computed, never materialized). Measured
// plateau 85.6-86.7% of 8 TB/s across {MLP 1/4/8} x {256/512/1024 thr} x
// {cs/wt} x {occ 49-79%} -> 148.4-153.4 us ncu / 156.1-157.8 us wall. This is
// the 1:1 R/W-stream ceiling of the LTS/HBM path (path-independent per the
// B300 model: LDG.cv == TMA at the ~6300 B/cyc LTS cap). Config below is the
// best measured point: MLP_p1=4, 256 thr, regs 32, 8 CTAs/SM, exact grid,
// bit-exact slope construction (rel_err = 0.0).

static constexpr int L_LOG2 = 11;                  // L = 2048
static constexpr int NH_MASK = 15;                 // NH = 16
static constexpr unsigned N_VEC = 1u << 25;        // 2^27 elems / 4
static constexpr int THREADS = 256;
static constexpr int VPT = 4;                      // float4 per thread (64 B)
// N_VEC / (THREADS*VPT) = 32768 exactly -> no tail, no bounds check

__device__ __forceinline__ float alibi_slope(int h) {
    // slope = 2^(-0.5*(h+1)).  e = (h+1)>>1 full halvings; odd (h+1) adds sqrt(1/2).
    int hp1 = h + 1;
    int e = hp1 >> 1;                                  // 0..8
    float p = __uint_as_float((unsigned)(127 - e) << 23);   // exact 2^-e
    return (hp1 & 1) ? p * 0.70710678118654752f : p;   // * sqrt(1/2) if odd
}

__global__ __launch_bounds__(THREADS)
void alibi_kernel(const float4* __restrict__ mask, float4* __restrict__ out) {
    const unsigned v0 = blockIdx.x * (THREADS * VPT) + threadIdx.x;

    // front-batched independent loads (MLP_p1 = 4), immediate offsets off one base
    const float4* __restrict__ src = mask + v0;
    float4 m[VPT];
#pragma unroll
    for (int k = 0; k < VPT; k++)
        m[k] = __ldcs(src + k * THREADS);

    float4* __restrict__ dst = out + v0;
#pragma unroll
    for (int k = 0; k < VPT; k++) {
        unsigned idx = (v0 + (unsigned)(k * THREADS)) << 2;   // elem index < 2^27
        int j = (int)(idx & ((1u << L_LOG2) - 1u));
        int i = (int)((idx >> L_LOG2) & ((1u << L_LOG2) - 1u));
        int h = (int)((idx >> (2 * L_LOG2)) & NH_MASK);

        float slope = alibi_slope(h);
        float base  = (float)(i - j);

        float4 r;
        r.x = m[k].x - fabsf(slope * (base - 0.0f));
        r.y = m[k].y - fabsf(slope * (base - 1.0f));
        r.z = m[k].z - fabsf(slope * (base - 2.0f));
        r.w = m[k].w - fabsf(slope * (base - 3.0f));
        __stcs(dst + k * THREADS, r);
    }
}

extern "C" void kernel_launch(void* const* d_in, const int* in_sizes, int n_in,
                              void* d_out, int out_size) {
    const float4* mask = (const float4*)d_in[0];
    float4* out = (float4*)d_out;

    const unsigned blocks = N_VEC / (THREADS * VPT);   // 32768
    alibi_kernel<<<blocks, THREADS>>>(mask, out);
}

// round 13
// speedup vs baseline: 1.0004x; 1.0004x over previous
#include <cuda_runtime.h>
#include <cstdint>

// out[b,h,i,j] = mask[b,h,i,j] - |slope[h] * (i - j)|
// B=2, NH=16, L=2048 -> 134,217,728 fp32 = 33,554,432 float4
// slope[h] = 2^(-0.5*(h+1)) for NH=16
//
// FINAL. Pure HBM-streaming kernel: 512 MiB read + 512 MiB write (compulsory
// minimum; bias register-computed). Measured plateau 85.6-86.7% of 8 TB/s
// across {MLP 1/4/8} x {256/512/1024 thr} x {cs/wt} x {occ 49-79%} — the 1:1
// R/W-stream ceiling of the LTS/HBM path (~6250 B/cyc, path-independent).
// Config: MLP_p1=4, 256 thr, 8 CTAs/SM, exact grid, bit-exact slopes.
//
// h is constant per block: elems/block = 256*4*4 = 4096 = 2^12, so
// elem_base = blockIdx.x << 12 and h = (elem_base >> 22) & 15
//           = (blockIdx.x >> 10) & 15.        (R10 bug: used >>12. Fixed.)

static constexpr int L_LOG2 = 11;                  // L = 2048
static constexpr unsigned N_VEC = 1u << 25;        // 2^27 elems / 4
static constexpr int THREADS = 256;
static constexpr int VPT = 4;                      // float4 per thread (64 B)
// N_VEC / (THREADS*VPT) = 32768 exactly -> no tail, no bounds check

__device__ __forceinline__ float alibi_slope(int h) {
    // slope = 2^(-0.5*(h+1)), bit-exact (matches fp32 reference exactly).
    int hp1 = h + 1;
    int e = hp1 >> 1;                                  // 0..8
    float p = __uint_as_float((unsigned)(127 - e) << 23);   // exact 2^-e
    return (hp1 & 1) ? p * 0.70710678118654752f : p;   // * sqrt(1/2) if odd
}

__global__ __launch_bounds__(THREADS)
void alibi_kernel(const float4* __restrict__ mask, float4* __restrict__ out) {
    const unsigned v0 = blockIdx.x * (THREADS * VPT) + threadIdx.x;

    // h and slope are uniform across the block
    const int h = (int)((blockIdx.x >> 10) & 15u);
    const float slope = alibi_slope(h);

    // front-batched independent loads (MLP_p1 = 4), immediate offsets off one base
    const float4* __restrict__ src = mask + v0;
    float4 m[VPT];
#pragma unroll
    for (int k = 0; k < VPT; k++)
        m[k] = __ldcs(src + k * THREADS);

    float4* __restrict__ dst = out + v0;
#pragma unroll
    for (int k = 0; k < VPT; k++) {
        unsigned idx = (v0 + (unsigned)(k * THREADS)) << 2;   // elem index < 2^27
        int j = (int)(idx & ((1u << L_LOG2) - 1u));
        int i = (int)((idx >> L_LOG2) & ((1u << L_LOG2) - 1u));
        float base = (float)(i - j);

        float4 r;
        r.x = m[k].x - fabsf(slope * (base - 0.0f));
        r.y = m[k].y - fabsf(slope * (base - 1.0f));
        r.z = m[k].z - fabsf(slope * (base - 2.0f));
        r.w = m[k].w - fabsf(slope * (base - 3.0f));
        __stcs(dst + k * THREADS, r);
    }
}

extern "C" void kernel_launch(void* const* d_in, const int* in_sizes, int n_in,
                              void* d_out, int out_size) {
    const float4* mask = (const float4*)d_in[0];
    float4* out = (float4*)d_out;

    const unsigned blocks = N_VEC / (THREADS * VPT);   // 32768
    alibi_kernel<<<blocks, THREADS>>>(mask, out);
}